// round 11
// baseline (speedup 1.0000x reference)
#include <cuda_runtime.h>
#include <cstddef>

typedef unsigned long long ull;

#define NTHREADS 256
#define TROWS 64

// ======== transposed-weight global scratch: Wt[j][k] per layer ========
__device__ __align__(16) float g_wt[65536];
__constant__ int c_pre[10]  = {0,4096,8192,12288,18688,25088,31488,52224,61440,65536};
__constant__ int c_nin[9]   = {64,64,64,80,80,80,144,144,64};
__constant__ int c_nout[9]  = {64,64,64,80,80,80,144,64,64};

__global__ void prep_kernel(const float* w0,const float* w1,const float* w2,
                            const float* w3,const float* w4,const float* w5,
                            const float* w6,const float* w7,const float* w8)
{
    const float* W[9] = {w0,w1,w2,w3,w4,w5,w6,w7,w8};
    int i = blockIdx.x * blockDim.x + threadIdx.x;
    if (i >= 65536) return;
    int s = 0;
    while (i >= c_pre[s + 1]) s++;
    int l = i - c_pre[s];
    int nin = c_nin[s], nout = c_nout[s];
    int j = l / nin, k = l - j * nin;
    g_wt[i] = W[s][k * nout + j];
}

// ======== packed fp32x2 + cp.async helpers ========
__device__ __forceinline__ ull ffma2(ull a, ull b, ull c) {
    ull d; asm("fma.rn.f32x2 %0, %1, %2, %3;" : "=l"(d) : "l"(a), "l"(b), "l"(c)); return d;
}
__device__ __forceinline__ float2 u2f(ull a) {
    float2 f; asm("mov.b64 {%0, %1}, %2;" : "=f"(f.x), "=f"(f.y) : "l"(a)); return f;
}
__device__ __forceinline__ float lrelu(float v) { return v > 0.0f ? v : 0.01f * v; }
__device__ __forceinline__ void cpa16(float* dst, const float* src) {
    unsigned sa = (unsigned)__cvta_generic_to_shared(dst);
    asm volatile("cp.async.cg.shared.global [%0], [%1], 16;" :: "r"(sa), "l"(src));
}
#define CPA_COMMIT() asm volatile("cp.async.commit_group;" ::: "memory")
#define CPA_WAIT0()  asm volatile("cp.async.wait_group 0;"  ::: "memory")

// ======== epilogue chunk maps ========
__constant__ int c_kind[31] = {0,0,0,0,0,0,0,0,0,0,0,0,1,1,1,1,0,0,0,1,0,0,0,0,0,1,1,1,1,1,1};
__constant__ int c_A[31]    = {320,152,304,304,304,304,304,152,152,152,152,152,
                               40,41,42,43, 152,208,416, 39, 208,152,416,360,152,
                               44,45,46,47,48,49};
__constant__ int c_B[31]    = {18,20,22,23,24,25,26,27,28,29,30,31,
                               0,2,3,5, 35,36,37, 1, 32,33,34,19,38,
                               4,4,4,4,4,4};
// blob: suit@0(40) rank@40(112) pos@152(56) action@208(96) active@304(16)
//       street@320(40) numpl@360(56) blind@416(16)

// ======== shared layout (floats) ========
#define OFF_BLOB 0                   // 432
#define OFF_SW   432                 // 48
#define OFF_SB   480                 // 48
#define OFF_BIAS 528                 // 704 (ends 1232)
#define OFF_A    1232                // 64*84 = 5376 (stride 84)
#define OFF_B    6608                // 64*84 = 5376
#define OFF_C    11984               // 64*148 = 9472 (stride 148)
#define OFF_W    21456               // 2 slots * 3584
#define SLOTF    3584
#define SMEM_FLOATS 28624
#define SMEM_BYTES  (SMEM_FLOATS * 4)  // 114496 -> 2 CTAs/SM
// D (144-wide, stride 148) overlays A+B (10752 >= 9472)

// ======== dense (sub-)layer, cp.async double-buffered weights (R6 pipeline) ========
// Xs[row][k] stride SIN; Wtg = transposed weights [NJ][NIN] row-major;
// writes Ys[row][JOFF+j] stride SOUT. Warp w owns j-tile of NJ/8 cols.
template<int NIN, int SIN, int NJ, int SOUT, int JOFF, int KC, bool ACT>
__device__ __forceinline__ void layer(const float* __restrict__ Xs, float* __restrict__ Ys,
                                      const float* __restrict__ Wtg,
                                      const float* __restrict__ bsm,
                                      float* __restrict__ Wslots)
{
    const int t = threadIdx.x, L = t & 31, wid = t >> 5;
    constexpr int TILEJ = NJ / 8;
    constexpr int WS  = KC + 4;
    constexpr int NCH = NIN / KC;
    constexpr int PER = KC / 4;
    const int j0 = wid * TILEJ;

    ull acc[TILEJ][2];
    #pragma unroll
    for (int j = 0; j < TILEJ; j++) { acc[j][0] = 0ull; acc[j][1] = 0ull; }

    const float* x0 = Xs + L * SIN;
    const float* x1 = Xs + (L + 32) * SIN;

    // ---- stage chunk 0 ----
    {
        for (int i = t; i < NJ * PER; i += NTHREADS) {
            int j = i / PER, k4 = (i - j * PER) << 2;
            cpa16(Wslots + j * WS + k4, Wtg + j * NIN + k4);
        }
        CPA_COMMIT(); CPA_WAIT0();
    }
    __syncthreads();

    #pragma unroll
    for (int c = 0; c < NCH; c++) {
        if (c + 1 < NCH) {  // stage next chunk into other slot (overlapped)
            float* dst = Wslots + ((c + 1) & 1) * SLOTF;
            const float* src = Wtg + (c + 1) * KC;
            for (int i = t; i < NJ * PER; i += NTHREADS) {
                int j = i / PER, k4 = (i - j * PER) << 2;
                cpa16(dst + j * WS + k4, src + j * NIN + k4);
            }
            CPA_COMMIT();
        }
        // ---- compute chunk c ----
        {
            const float* Wt = Wslots + (c & 1) * SLOTF;
            const float* xk0 = x0 + c * KC;
            const float* xk1 = x1 + c * KC;
            const float* wr0 = Wt + j0 * WS;
            #pragma unroll 4
            for (int k = 0; k < KC; k += 4) {
                ulonglong2 xa = *reinterpret_cast<const ulonglong2*>(xk0 + k);
                ulonglong2 xb = *reinterpret_cast<const ulonglong2*>(xk1 + k);
                const float* wr = wr0 + k;
                #pragma unroll
                for (int j = 0; j < TILEJ; j++) {
                    ulonglong2 wv = *reinterpret_cast<const ulonglong2*>(wr + j * WS);
                    acc[j][0] = ffma2(xa.x, wv.x, acc[j][0]);
                    acc[j][0] = ffma2(xa.y, wv.y, acc[j][0]);
                    acc[j][1] = ffma2(xb.x, wv.x, acc[j][1]);
                    acc[j][1] = ffma2(xb.y, wv.y, acc[j][1]);
                }
            }
        }
        if (c + 1 < NCH) CPA_WAIT0();
        __syncthreads();
    }

    // ---- epilogue: horizontal add + bias (+act) ----
    #pragma unroll
    for (int j = 0; j < TILEJ; j += 2) {
        float b0 = bsm[j0 + j], b1 = bsm[j0 + j + 1];
        #pragma unroll
        for (int r = 0; r < 2; r++) {
            float2 s0 = u2f(acc[j][r]);
            float2 s1 = u2f(acc[j + 1][r]);
            float v0 = s0.x + s0.y + b0;
            float v1 = s1.x + s1.y + b1;
            if (ACT) { v0 = lrelu(v0); v1 = lrelu(v1); }
            *reinterpret_cast<float2*>(Ys + (L + 32 * r) * SOUT + JOFF + j0 + j) =
                make_float2(v0, v1);
        }
    }
}

// final 64->64 layer: no activation, writes out cols [0,64)
__device__ __forceinline__ void layer_final(const float* __restrict__ Xs,
                                            const float* __restrict__ Wtg,
                                            const float* __restrict__ bsm,
                                            float* __restrict__ Wslots,
                                            float* __restrict__ out, size_t g0)
{
    const int t = threadIdx.x, L = t & 31, wid = t >> 5;
    constexpr int KC = 32, WS = 36, NCH = 2, PER = 8;
    const int j0 = wid * 8;

    ull acc[8][2];
    #pragma unroll
    for (int j = 0; j < 8; j++) { acc[j][0] = 0ull; acc[j][1] = 0ull; }

    const float* x0 = Xs + L * 148;
    const float* x1 = Xs + (L + 32) * 148;

    {
        for (int i = t; i < 64 * PER; i += NTHREADS) {
            int j = i / PER, k4 = (i - j * PER) << 2;
            cpa16(Wslots + j * WS + k4, Wtg + j * 64 + k4);
        }
        CPA_COMMIT(); CPA_WAIT0();
    }
    __syncthreads();

    #pragma unroll
    for (int c = 0; c < NCH; c++) {
        if (c + 1 < NCH) {
            float* dst = Wslots + SLOTF;
            const float* src = Wtg + KC;
            for (int i = t; i < 64 * PER; i += NTHREADS) {
                int j = i / PER, k4 = (i - j * PER) << 2;
                cpa16(dst + j * WS + k4, src + j * 64 + k4);
            }
            CPA_COMMIT();
        }
        {
            const float* Wt = Wslots + (c & 1) * SLOTF;
            const float* xk0 = x0 + c * KC;
            const float* xk1 = x1 + c * KC;
            const float* wr0 = Wt + j0 * WS;
            #pragma unroll 4
            for (int k = 0; k < KC; k += 4) {
                ulonglong2 xa = *reinterpret_cast<const ulonglong2*>(xk0 + k);
                ulonglong2 xb = *reinterpret_cast<const ulonglong2*>(xk1 + k);
                const float* wr = wr0 + k;
                #pragma unroll
                for (int j = 0; j < 8; j++) {
                    ulonglong2 wv = *reinterpret_cast<const ulonglong2*>(wr + j * WS);
                    acc[j][0] = ffma2(xa.x, wv.x, acc[j][0]);
                    acc[j][0] = ffma2(xa.y, wv.y, acc[j][0]);
                    acc[j][1] = ffma2(xb.x, wv.x, acc[j][1]);
                    acc[j][1] = ffma2(xb.y, wv.y, acc[j][1]);
                }
            }
        }
        if (c + 1 < NCH) CPA_WAIT0();
        __syncthreads();
    }

    #pragma unroll
    for (int r = 0; r < 2; r++) {
        float v[8];
        #pragma unroll
        for (int j = 0; j < 8; j++) {
            float2 s = u2f(acc[j][r]);
            v[j] = s.x + s.y + bsm[j0 + j];
        }
        float* op = out + (g0 + L + 32 * r) * 312 + j0;
        *reinterpret_cast<float4*>(op)     = make_float4(v[0], v[1], v[2], v[3]);
        *reinterpret_cast<float4*>(op + 4) = make_float4(v[4], v[5], v[6], v[7]);
    }
}

__global__ void __launch_bounds__(NTHREADS, 2)
preproc_kernel(const float* __restrict__ state,
               const float* __restrict__ suit_emb, const float* __restrict__ rank_emb,
               const float* __restrict__ hb1, const float* __restrict__ hb2,
               const float* __restrict__ hb3, const float* __restrict__ bb1,
               const float* __restrict__ bb2, const float* __restrict__ bb3,
               const float* __restrict__ cb1, const float* __restrict__ cb2,
               const float* __restrict__ cb3,
               const float* __restrict__ pos_emb, const float* __restrict__ action_emb,
               const float* __restrict__ active_emb, const float* __restrict__ street_emb,
               const float* __restrict__ numpl_emb, const float* __restrict__ blind_emb,
               const float* __restrict__ scalar_W, const float* __restrict__ scalar_b,
               float* __restrict__ out)
{
    extern __shared__ float smem[];
    float* blob = smem + OFF_BLOB;
    float* sW   = smem + OFF_SW;
    float* sB   = smem + OFF_SB;
    float* bias = smem + OFF_BIAS;
    float* A    = smem + OFF_A;      // stride 84
    float* Bb   = smem + OFF_B;      // stride 84
    float* C    = smem + OFF_C;      // stride 148
    float* D    = smem + OFF_A;      // stride 148 (overlays A+B)
    float* W    = smem + OFF_W;

    const int t = threadIdx.x;
    const size_t g0 = (size_t)blockIdx.x * TROWS;
    const float* st = state + g0 * 50;

    // ---- stage tables + biases ----
    for (int i = t; i < 40;  i += NTHREADS) blob[0   + i] = suit_emb[i];
    for (int i = t; i < 112; i += NTHREADS) blob[40  + i] = rank_emb[i];
    for (int i = t; i < 56;  i += NTHREADS) blob[152 + i] = pos_emb[i];
    for (int i = t; i < 96;  i += NTHREADS) blob[208 + i] = action_emb[i];
    for (int i = t; i < 16;  i += NTHREADS) blob[304 + i] = active_emb[i];
    for (int i = t; i < 40;  i += NTHREADS) blob[320 + i] = street_emb[i];
    for (int i = t; i < 56;  i += NTHREADS) blob[360 + i] = numpl_emb[i];
    for (int i = t; i < 16;  i += NTHREADS) blob[416 + i] = blind_emb[i];
    for (int i = t; i < 48;  i += NTHREADS) { sW[i] = scalar_W[i]; sB[i] = scalar_b[i]; }
    for (int i = t; i < 64;  i += NTHREADS) bias[0   + i] = hb1[i];
    for (int i = t; i < 64;  i += NTHREADS) bias[64  + i] = hb2[i];
    for (int i = t; i < 64;  i += NTHREADS) bias[128 + i] = hb3[i];
    for (int i = t; i < 80;  i += NTHREADS) bias[192 + i] = bb1[i];
    for (int i = t; i < 80;  i += NTHREADS) bias[272 + i] = bb2[i];
    for (int i = t; i < 80;  i += NTHREADS) bias[352 + i] = bb3[i];
    for (int i = t; i < 144; i += NTHREADS) bias[432 + i] = cb1[i];
    for (int i = t; i < 64;  i += NTHREADS) bias[576 + i] = cb2[i];
    for (int i = t; i < 64;  i += NTHREADS) bias[640 + i] = cb3[i];
    __syncthreads();

    const float4* blob4 = reinterpret_cast<const float4*>(blob);

    // ---- cheap output columns 64..311: coalesced float4 stores ----
    // thread i -> row r = i/62, quad q = i%62; lanes hit consecutive out addresses
    for (int i = t; i < 64 * 62; i += NTHREADS) {
        int r = i / 62, q = i - r * 62;
        int ch = q >> 1, half = q & 1;
        int kind = c_kind[ch], Ai = c_A[ch], Bc = c_B[ch];
        float4 v;
        if (kind == 0) {
            int xi = (int)__ldg(st + r * 50 + Bc);
            v = blob4[(Ai >> 2) + xi * 2 + half];
        } else {
            float s = __ldg(st + r * 50 + Ai);
            float4 w = *reinterpret_cast<const float4*>(sW + Bc * 8 + half * 4);
            float4 p = *reinterpret_cast<const float4*>(sB + Bc * 8 + half * 4);
            v = make_float4(s * w.x + p.x, s * w.y + p.y, s * w.z + p.z, s * w.w + p.w);
        }
        *reinterpret_cast<float4*>(out + (g0 + r) * 312 + 64 + q * 4) = v;
    }

    // ---- gather hand input (4 cards x 16 feats) -> A, vectorized ----
    {
        int r = t >> 2, c = t & 3;  // 256 threads = 64 rows x 4 cards
        int s  = (int)__ldg(st + r * 50 + 2 * c + 1);
        int rk = (int)__ldg(st + r * 50 + 2 * c);
        float* ap = A + r * 84 + c * 16;
        *reinterpret_cast<float4*>(ap)      = blob4[s * 2];
        *reinterpret_cast<float4*>(ap + 4)  = blob4[s * 2 + 1];
        *reinterpret_cast<float4*>(ap + 8)  = blob4[10 + rk * 2];
        *reinterpret_cast<float4*>(ap + 12) = blob4[10 + rk * 2 + 1];
    }
    // (h1's chunk-0 stage barrier establishes visibility of A)

    layer<64, 84, 64, 84,  0,  32, true >(A,  Bb, g_wt + 0,     bias + 0,   W);
    layer<64, 84, 64, 84,  0,  32, true >(Bb, A,  g_wt + 4096,  bias + 64,  W);
    layer<64, 84, 64, 148, 0,  32, false>(A,  C,  g_wt + 8192,  bias + 128, W);

    __syncthreads();  // h3 done reading A before board gather overwrites

    // ---- gather board input (5 cards x 16 feats) -> A, vectorized ----
    for (int i = t; i < 64 * 8; i += NTHREADS) {
        int r = i >> 3, c = i & 7;
        if (c < 5) {
            int s  = (int)__ldg(st + r * 50 + 9 + 2 * c);
            int rk = (int)__ldg(st + r * 50 + 8 + 2 * c);
            float* ap = A + r * 84 + c * 16;
            *reinterpret_cast<float4*>(ap)      = blob4[s * 2];
            *reinterpret_cast<float4*>(ap + 4)  = blob4[s * 2 + 1];
            *reinterpret_cast<float4*>(ap + 8)  = blob4[10 + rk * 2];
            *reinterpret_cast<float4*>(ap + 12) = blob4[10 + rk * 2 + 1];
        }
    }

    layer<80, 84, 80, 84,  0,  40, true >(A,  Bb, g_wt + 12288, bias + 192, W);
    layer<80, 84, 80, 84,  0,  40, true >(Bb, A,  g_wt + 18688, bias + 272, W);
    layer<80, 84, 80, 148, 64, 40, false>(A,  C,  g_wt + 25088, bias + 352, W);

    // ---- combined MLP: C[144] -> D[144] -> C[0:64) -> out ----
    layer<144, 148, 80, 148, 0,  36, true>(C, D, g_wt + 31488,            bias + 432,      W);
    layer<144, 148, 64, 148, 80, 36, true>(C, D, g_wt + 31488 + 80 * 144, bias + 432 + 80, W);
    layer<144, 148, 64, 148, 0,  48, true>(D, C, g_wt + 52224,            bias + 576,      W);
    layer_final(C, g_wt + 61440, bias + 640, W, out, g0);
}

extern "C" void kernel_launch(void* const* d_in, const int* in_sizes, int n_in,
                              void* d_out, int out_size)
{
    (void)n_in; (void)out_size;
    cudaFuncSetAttribute(preproc_kernel, cudaFuncAttributeMaxDynamicSharedMemorySize, SMEM_BYTES);

    // one-time-per-graph weight transpose into g_wt
    prep_kernel<<<256, 256>>>(
        (const float*)d_in[3],  (const float*)d_in[5],  (const float*)d_in[7],
        (const float*)d_in[9],  (const float*)d_in[11], (const float*)d_in[13],
        (const float*)d_in[15], (const float*)d_in[17], (const float*)d_in[19]);

    const int nrows = in_sizes[0] / 50;     // 262144
    const int grid  = nrows / TROWS;        // 4096

    preproc_kernel<<<grid, NTHREADS, SMEM_BYTES>>>(
        (const float*)d_in[0],
        (const float*)d_in[1],  (const float*)d_in[2],
        (const float*)d_in[4],  (const float*)d_in[6],  (const float*)d_in[8],
        (const float*)d_in[10], (const float*)d_in[12], (const float*)d_in[14],
        (const float*)d_in[16], (const float*)d_in[18], (const float*)d_in[20],
        (const float*)d_in[21], (const float*)d_in[22],
        (const float*)d_in[23], (const float*)d_in[24],
        (const float*)d_in[25], (const float*)d_in[26],
        (const float*)d_in[27], (const float*)d_in[28],
        (float*)d_out);
}

// round 12
// speedup vs baseline: 1.2707x; 1.2707x over previous
#include <cuda_runtime.h>
#include <cuda_bf16.h>
#include <cstddef>
#include <cstdint>

typedef __nv_bfloat16 bf16;

#define NTHREADS 256
#define TROWS 32

// ======== global bf16 split-weight images (transposed [NOUT][NIN] per segment) ========
__device__ __align__(16) bf16 g_wh[65536];
__device__ __align__(16) bf16 g_wl[65536];

__constant__ int c_pre[10]  = {0,4096,8192,12288,18688,25088,31488,52224,61440,65536};
__constant__ int c_nin[9]   = {64,64,64,80,80,80,144,144,64};
__constant__ int c_nout[9]  = {64,64,64,80,80,80,144,64,64};

__global__ void prep_kernel(const float* w0,const float* w1,const float* w2,
                            const float* w3,const float* w4,const float* w5,
                            const float* w6,const float* w7,const float* w8)
{
    const float* W[9] = {w0,w1,w2,w3,w4,w5,w6,w7,w8};
    int i = blockIdx.x * blockDim.x + threadIdx.x;
    if (i >= 65536) return;
    int s = 0;
    while (i >= c_pre[s + 1]) s++;
    int l = i - c_pre[s];
    int nin = c_nin[s], nout = c_nout[s];
    int j = l / nin, k = l - j * nin;
    float w = W[s][k * nout + j];
    bf16 h = __float2bfloat16_rn(w);
    bf16 lo = __float2bfloat16_rn(w - __bfloat162float(h));
    g_wh[i] = h;
    g_wl[i] = lo;
}

// ======== helpers ========
__device__ __forceinline__ float lrelu(float v) { return v > 0.0f ? v : 0.01f * v; }
__device__ __forceinline__ uint32_t s2u(const void* p) {
    return (uint32_t)__cvta_generic_to_shared(p);
}
__device__ __forceinline__ void cpa16(void* dst, const void* src) {
    asm volatile("cp.async.cg.shared.global [%0], [%1], 16;" :: "r"(s2u(dst)), "l"(src));
}
#define CPA_COMMIT() asm volatile("cp.async.commit_group;" ::: "memory")
#define CPA_WAIT0()  asm volatile("cp.async.wait_group 0;"  ::: "memory")

__device__ __forceinline__ void ldsm4(uint32_t a, uint32_t* r) {
    asm volatile("ldmatrix.sync.aligned.m8n8.x4.shared.b16 {%0,%1,%2,%3}, [%4];"
        : "=r"(r[0]), "=r"(r[1]), "=r"(r[2]), "=r"(r[3]) : "r"(a));
}
__device__ __forceinline__ void ldsm2(uint32_t a, uint32_t* r) {
    asm volatile("ldmatrix.sync.aligned.m8n8.x2.shared.b16 {%0,%1}, [%2];"
        : "=r"(r[0]), "=r"(r[1]) : "r"(a));
}
__device__ __forceinline__ void mma16816(float* d, const uint32_t* a, const uint32_t* b) {
    asm volatile("mma.sync.aligned.m16n8k16.row.col.f32.bf16.bf16.f32 "
        "{%0,%1,%2,%3}, {%4,%5,%6,%7}, {%8,%9}, {%0,%1,%2,%3};"
        : "+f"(d[0]), "+f"(d[1]), "+f"(d[2]), "+f"(d[3])
        : "r"(a[0]), "r"(a[1]), "r"(a[2]), "r"(a[3]), "r"(b[0]), "r"(b[1]));
}

// ======== epilogue chunk maps ========
__constant__ int c_kind[31] = {0,0,0,0,0,0,0,0,0,0,0,0,1,1,1,1,0,0,0,1,0,0,0,0,0,1,1,1,1,1,1};
__constant__ int c_A[31]    = {320,152,304,304,304,304,304,152,152,152,152,152,
                               40,41,42,43, 152,208,416, 39, 208,152,416,360,152,
                               44,45,46,47,48,49};
__constant__ int c_B[31]    = {18,20,22,23,24,25,26,27,28,29,30,31,
                               0,2,3,5, 35,36,37, 1, 32,33,34,19,38,
                               4,4,4,4,4,4};
// blob: suit@0(40) rank@40(112) pos@152(56) action@208(96) active@304(16)
//       street@320(40) numpl@360(56) blind@416(16)

// ======== shared layout (bytes) ========
// fp32 region: blob 432f @0, sW 48f @432, sB 48f @480, bias 704f @528 -> 1232f = 4928B
#define B_P0H   4928
#define PLANEB  11776              /* 32 rows * 368B */
#define B_P0L   (B_P0H + PLANEB)
#define B_P1H   (B_P0L + PLANEB)
#define B_P1L   (B_P1H + PLANEB)
#define B_W     (B_P1L + PLANEB)   /* 52032 */
#define SLOTB   23040              /* 144 rows * 80B * 2 planes */
#define WLO     11520
#define SMEM_BYTES (B_W + 2 * SLOTB)  /* 98112 -> 2 CTAs/SM */
#define PSTR    184                /* plane row stride in bf16 (368B, odd*16B: LDSM conflict-free) */
#define WSTR    40                 /* weight slot row stride in bf16 (80B, odd*16B) */

// split fp32 -> (hi, lo) bf16 pair-stores into both planes
__device__ __forceinline__ void split_store(bf16* H, bf16* Lp, int row, int k,
                                            float v0, float v1)
{
    bf16 h0 = __float2bfloat16_rn(v0), h1 = __float2bfloat16_rn(v1);
    bf16 l0 = __float2bfloat16_rn(v0 - __bfloat162float(h0));
    bf16 l1 = __float2bfloat16_rn(v1 - __bfloat162float(h1));
    uint32_t ph = (uint32_t)__bfloat16_as_ushort(h0) | ((uint32_t)__bfloat16_as_ushort(h1) << 16);
    uint32_t pl = (uint32_t)__bfloat16_as_ushort(l0) | ((uint32_t)__bfloat16_as_ushort(l1) << 16);
    *reinterpret_cast<uint32_t*>(H  + row * PSTR + k) = ph;
    *reinterpret_cast<uint32_t*>(Lp + row * PSTR + k) = pl;
}

// stage one k-chunk (cur = 32 or 16) of both weight planes into a slot
__device__ __forceinline__ void stage_w(char* smem, int slot,
                                        const bf16* gh, const bf16* gl,
                                        int nin, int nout, int kc, int cur)
{
    bf16* sh = reinterpret_cast<bf16*>(smem + B_W + slot * SLOTB);
    bf16* sl = reinterpret_cast<bf16*>(smem + B_W + slot * SLOTB + WLO);
    int per = cur >> 3;  // 16B units per row
    int tot = nout * per;
    for (int i = threadIdx.x; i < tot; i += NTHREADS) {
        int n = i / per, q = i - n * per;
        cpa16(sh + n * WSTR + q * 8, gh + n * nin + kc + q * 8);
        cpa16(sl + n * WSTR + q * 8, gl + n * nin + kc + q * 8);
    }
    CPA_COMMIT();
}

// ======== one dense layer on tensor cores (3-pass bf16 split) ========
template<int NIN, int NOUT, bool ACT, bool FINAL>
__device__ __forceinline__ void layer_mma(
    const bf16* __restrict__ srcH, const bf16* __restrict__ srcL,
    bf16* __restrict__ dstH, bf16* __restrict__ dstL,
    const bf16* __restrict__ gwh, const bf16* __restrict__ gwl,
    const float* __restrict__ bsm, char* smem,
    float* __restrict__ out, size_t g0)
{
    const int t = threadIdx.x, L = t & 31, wid = t >> 5;
    const int mb = wid & 1, ng = wid >> 1;          // 2 m-blocks x 4 n-groups
    constexpr int NB = NOUT / 8;
    constexpr int MAXNB = (NB + 3) / 4;

    float acc[MAXNB][4];
    #pragma unroll
    for (int i = 0; i < MAXNB; i++)
        #pragma unroll
        for (int q = 0; q < 4; q++) acc[i][q] = 0.0f;

    // A lane addressing: row = mb*16 + L%16, col8 = (L/16)*8
    const int arow = mb * 16 + (L & 15);
    const uint32_t uAH = s2u(srcH + arow * PSTR + ((L >> 4) << 3));
    const uint32_t uAL = s2u(srcL + arow * PSTR + ((L >> 4) << 3));
    // B lane addressing within a slot: n-row = L%8 (+nb*8), k8 = ((L/8)&1)*8
    const int bofs_lane = ((L & 7) * WSTR + (((L >> 3) & 1) << 3)) * 2;  // bytes

    stage_w(smem, 0, gwh, gwl, NIN, NOUT, 0, NIN >= 32 ? 32 : NIN);
    CPA_WAIT0();
    __syncthreads();

    int slot = 0;
    for (int kc = 0; kc < NIN; kc += 32, slot ^= 1) {
        int cur = NIN - kc; if (cur > 32) cur = 32;
        if (kc + 32 < NIN) {
            int nx = NIN - kc - 32; if (nx > 32) nx = 32;
            stage_w(smem, slot ^ 1, gwh, gwl, NIN, NOUT, kc + 32, nx);
        }
        uint32_t uBH = s2u(smem + B_W + slot * SLOTB) + bofs_lane;
        uint32_t uBL = uBH + WLO;
        for (int kb = 0; kb < cur; kb += 16) {
            uint32_t ah[4], al[4];
            ldsm4(uAH + (kc + kb) * 2, ah);
            ldsm4(uAL + (kc + kb) * 2, al);
            #pragma unroll
            for (int i = 0; i < MAXNB; i++) {
                int nb = ng + 4 * i;
                if (nb < NB) {
                    uint32_t bo = (uint32_t)(nb * 8 * WSTR + kb) * 2;
                    uint32_t bh[2], bl[2];
                    ldsm2(uBH + bo, bh);
                    ldsm2(uBL + bo, bl);
                    mma16816(acc[i], ah, bh);   // xh * wh
                    mma16816(acc[i], ah, bl);   // xh * wl
                    mma16816(acc[i], al, bh);   // xl * wh
                }
            }
        }
        CPA_WAIT0();
        __syncthreads();
    }

    // epilogue: D frag (r0 = L/4, c0 = 2(L%4); rows r0, r0+8)
    const int r0 = L >> 2, c0 = (L & 3) * 2;
    const int gr0 = mb * 16 + r0, gr1 = gr0 + 8;
    #pragma unroll
    for (int i = 0; i < MAXNB; i++) {
        int nb = ng + 4 * i;
        if (nb < NB) {
            int n0 = nb * 8 + c0;
            float b0 = bsm[n0], b1 = bsm[n0 + 1];
            float v00 = acc[i][0] + b0, v01 = acc[i][1] + b1;
            float v10 = acc[i][2] + b0, v11 = acc[i][3] + b1;
            if (ACT) { v00 = lrelu(v00); v01 = lrelu(v01); v10 = lrelu(v10); v11 = lrelu(v11); }
            if (FINAL) {
                *reinterpret_cast<float2*>(out + (g0 + gr0) * 312 + n0) = make_float2(v00, v01);
                *reinterpret_cast<float2*>(out + (g0 + gr1) * 312 + n0) = make_float2(v10, v11);
            } else {
                split_store(dstH, dstL, gr0, n0, v00, v01);
                split_store(dstH, dstL, gr1, n0, v10, v11);
            }
        }
    }
    __syncthreads();
}

__global__ void __launch_bounds__(NTHREADS, 2)
preproc_kernel(const float* __restrict__ state,
               const float* __restrict__ suit_emb, const float* __restrict__ rank_emb,
               const float* __restrict__ hb1, const float* __restrict__ hb2,
               const float* __restrict__ hb3, const float* __restrict__ bb1,
               const float* __restrict__ bb2, const float* __restrict__ bb3,
               const float* __restrict__ cb1, const float* __restrict__ cb2,
               const float* __restrict__ cb3,
               const float* __restrict__ pos_emb, const float* __restrict__ action_emb,
               const float* __restrict__ active_emb, const float* __restrict__ street_emb,
               const float* __restrict__ numpl_emb, const float* __restrict__ blind_emb,
               const float* __restrict__ scalar_W, const float* __restrict__ scalar_b,
               float* __restrict__ out)
{
    extern __shared__ __align__(16) char smem[];
    float* fp   = reinterpret_cast<float*>(smem);
    float* blob = fp;
    float* sW   = fp + 432;
    float* sB   = fp + 480;
    float* bias = fp + 528;
    bf16* P0H = reinterpret_cast<bf16*>(smem + B_P0H);
    bf16* P0L = reinterpret_cast<bf16*>(smem + B_P0L);
    bf16* P1H = reinterpret_cast<bf16*>(smem + B_P1H);
    bf16* P1L = reinterpret_cast<bf16*>(smem + B_P1L);

    const int t = threadIdx.x;
    const size_t g0 = (size_t)blockIdx.x * TROWS;
    const float* st = state + g0 * 50;

    // ---- stage tables + biases ----
    for (int i = t; i < 40;  i += NTHREADS) blob[0   + i] = suit_emb[i];
    for (int i = t; i < 112; i += NTHREADS) blob[40  + i] = rank_emb[i];
    for (int i = t; i < 56;  i += NTHREADS) blob[152 + i] = pos_emb[i];
    for (int i = t; i < 96;  i += NTHREADS) blob[208 + i] = action_emb[i];
    for (int i = t; i < 16;  i += NTHREADS) blob[304 + i] = active_emb[i];
    for (int i = t; i < 40;  i += NTHREADS) blob[320 + i] = street_emb[i];
    for (int i = t; i < 56;  i += NTHREADS) blob[360 + i] = numpl_emb[i];
    for (int i = t; i < 16;  i += NTHREADS) blob[416 + i] = blind_emb[i];
    for (int i = t; i < 48;  i += NTHREADS) { sW[i] = scalar_W[i]; sB[i] = scalar_b[i]; }
    for (int i = t; i < 64;  i += NTHREADS) bias[0   + i] = hb1[i];
    for (int i = t; i < 64;  i += NTHREADS) bias[64  + i] = hb2[i];
    for (int i = t; i < 64;  i += NTHREADS) bias[128 + i] = hb3[i];
    for (int i = t; i < 80;  i += NTHREADS) bias[192 + i] = bb1[i];
    for (int i = t; i < 80;  i += NTHREADS) bias[272 + i] = bb2[i];
    for (int i = t; i < 80;  i += NTHREADS) bias[352 + i] = bb3[i];
    for (int i = t; i < 144; i += NTHREADS) bias[432 + i] = cb1[i];
    for (int i = t; i < 64;  i += NTHREADS) bias[576 + i] = cb2[i];
    for (int i = t; i < 64;  i += NTHREADS) bias[640 + i] = cb3[i];
    __syncthreads();

    const float4* blob4 = reinterpret_cast<const float4*>(blob);

    // ---- cheap output columns 64..311: coalesced float4 stores ----
    for (int i = t; i < TROWS * 62; i += NTHREADS) {
        int r = i / 62, q = i - r * 62;
        int ch = q >> 1, half = q & 1;
        int kind = c_kind[ch], Ai = c_A[ch], Bc = c_B[ch];
        float4 v;
        if (kind == 0) {
            int xi = (int)__ldg(st + r * 50 + Bc);
            v = blob4[(Ai >> 2) + xi * 2 + half];
        } else {
            float s = __ldg(st + r * 50 + Ai);
            float4 w = *reinterpret_cast<const float4*>(sW + Bc * 8 + half * 4);
            float4 p = *reinterpret_cast<const float4*>(sB + Bc * 8 + half * 4);
            v = make_float4(s * w.x + p.x, s * w.y + p.y, s * w.z + p.z, s * w.w + p.w);
        }
        *reinterpret_cast<float4*>(out + (g0 + r) * 312 + 64 + q * 4) = v;
    }

    // ---- gather hand input (32 rows x 4 cards x 16 feats) -> P0 planes ----
    if (t < TROWS * 4) {
        int r = t >> 2, c = t & 3;
        int s  = (int)__ldg(st + r * 50 + 2 * c + 1);
        int rk = (int)__ldg(st + r * 50 + 2 * c);
        float v[16];
        *reinterpret_cast<float4*>(v)      = blob4[s * 2];
        *reinterpret_cast<float4*>(v + 4)  = blob4[s * 2 + 1];
        *reinterpret_cast<float4*>(v + 8)  = blob4[10 + rk * 2];
        *reinterpret_cast<float4*>(v + 12) = blob4[10 + rk * 2 + 1];
        #pragma unroll
        for (int p = 0; p < 8; p++)
            split_store(P0H, P0L, r, c * 16 + 2 * p, v[2 * p], v[2 * p + 1]);
    }
    // (visibility via h1's chunk-0 stage barrier)

    layer_mma<64, 64, true,  false>(P0H, P0L, P1H, P1L, g_wh + 0,    g_wl + 0,    bias + 0,   smem, out, g0);
    layer_mma<64, 64, true,  false>(P1H, P1L, P0H, P0L, g_wh + 4096, g_wl + 4096, bias + 64,  smem, out, g0);
    layer_mma<64, 64, false, false>(P0H, P0L, P1H, P1L, g_wh + 8192, g_wl + 8192, bias + 128, smem, out, g0);
    // hand output now in P1[k 0:64)

    // ---- gather board input (32 rows x 5 cards) -> P0 ----
    if (t < TROWS * 5) {
        int r = t / 5, c = t - r * 5;
        int s  = (int)__ldg(st + r * 50 + 9 + 2 * c);
        int rk = (int)__ldg(st + r * 50 + 8 + 2 * c);
        float v[16];
        *reinterpret_cast<float4*>(v)      = blob4[s * 2];
        *reinterpret_cast<float4*>(v + 4)  = blob4[s * 2 + 1];
        *reinterpret_cast<float4*>(v + 8)  = blob4[10 + rk * 2];
        *reinterpret_cast<float4*>(v + 12) = blob4[10 + rk * 2 + 1];
        #pragma unroll
        for (int p = 0; p < 8; p++)
            split_store(P0H, P0L, r, c * 16 + 2 * p, v[2 * p], v[2 * p + 1]);
    }

    layer_mma<80, 80, true,  false>(P0H, P0L, P1H + 64, P1L + 64, g_wh + 12288, g_wl + 12288, bias + 192, smem, out, g0);
    layer_mma<80, 80, true,  false>(P1H + 64, P1L + 64, P0H, P0L, g_wh + 18688, g_wl + 18688, bias + 272, smem, out, g0);
    layer_mma<80, 80, false, false>(P0H, P0L, P1H + 64, P1L + 64, g_wh + 25088, g_wl + 25088, bias + 352, smem, out, g0);
    // P1 now holds concat[hand(0:64), board(64:144)]

    layer_mma<144, 144, true, false>(P1H, P1L, P0H, P0L, g_wh + 31488, g_wl + 31488, bias + 432, smem, out, g0);
    layer_mma<144, 64,  true, false>(P0H, P0L, P1H, P1L, g_wh + 52224, g_wl + 52224, bias + 576, smem, out, g0);
    layer_mma<64,  64, false, true >(P1H, P1L, P0H, P0L, g_wh + 61440, g_wl + 61440, bias + 640, smem, out, g0);
}

extern "C" void kernel_launch(void* const* d_in, const int* in_sizes, int n_in,
                              void* d_out, int out_size)
{
    (void)n_in; (void)out_size;
    cudaFuncSetAttribute(preproc_kernel, cudaFuncAttributeMaxDynamicSharedMemorySize, SMEM_BYTES);

    // one-time-per-graph weight transpose + bf16 hi/lo split
    prep_kernel<<<256, 256>>>(
        (const float*)d_in[3],  (const float*)d_in[5],  (const float*)d_in[7],
        (const float*)d_in[9],  (const float*)d_in[11], (const float*)d_in[13],
        (const float*)d_in[15], (const float*)d_in[17], (const float*)d_in[19]);

    const int nrows = in_sizes[0] / 50;     // 262144
    const int grid  = nrows / TROWS;        // 8192

    preproc_kernel<<<grid, NTHREADS, SMEM_BYTES>>>(
        (const float*)d_in[0],
        (const float*)d_in[1],  (const float*)d_in[2],
        (const float*)d_in[4],  (const float*)d_in[6],  (const float*)d_in[8],
        (const float*)d_in[10], (const float*)d_in[12], (const float*)d_in[14],
        (const float*)d_in[16], (const float*)d_in[18], (const float*)d_in[20],
        (const float*)d_in[21], (const float*)d_in[22],
        (const float*)d_in[23], (const float*)d_in[24],
        (const float*)d_in[25], (const float*)d_in[26],
        (const float*)d_in[27], (const float*)d_in[28],
        (float*)d_out);
}

// round 13
// speedup vs baseline: 1.4305x; 1.1258x over previous
#include <cuda_runtime.h>
#include <cuda_bf16.h>
#include <cstddef>
#include <cstdint>

typedef __nv_bfloat16 bf16;

#define NTHREADS 256
#define TROWS 32

// ======== global bf16 split-weight images (transposed [NOUT][NIN] per segment) ========
__device__ __align__(16) bf16 g_wh[65536];
__device__ __align__(16) bf16 g_wl[65536];

__constant__ int c_pre[10]  = {0,4096,8192,12288,18688,25088,31488,52224,61440,65536};
__constant__ int c_nin[9]   = {64,64,64,80,80,80,144,144,64};
__constant__ int c_nout[9]  = {64,64,64,80,80,80,144,64,64};

__global__ void prep_kernel(const float* w0,const float* w1,const float* w2,
                            const float* w3,const float* w4,const float* w5,
                            const float* w6,const float* w7,const float* w8)
{
    const float* W[9] = {w0,w1,w2,w3,w4,w5,w6,w7,w8};
    int i = blockIdx.x * blockDim.x + threadIdx.x;
    if (i >= 65536) return;
    int s = 0;
    while (i >= c_pre[s + 1]) s++;
    int l = i - c_pre[s];
    int nin = c_nin[s], nout = c_nout[s];
    int j = l / nin, k = l - j * nin;
    float w = W[s][k * nout + j];
    bf16 h = __float2bfloat16_rn(w);
    bf16 lo = __float2bfloat16_rn(w - __bfloat162float(h));
    g_wh[i] = h;
    g_wl[i] = lo;
}

// ======== helpers ========
__device__ __forceinline__ float lrelu(float v) { return v > 0.0f ? v : 0.01f * v; }
__device__ __forceinline__ uint32_t s2u(const void* p) {
    return (uint32_t)__cvta_generic_to_shared(p);
}
__device__ __forceinline__ void cpa16(void* dst, const void* src) {
    asm volatile("cp.async.cg.shared.global [%0], [%1], 16;" :: "r"(s2u(dst)), "l"(src));
}
#define CPA_COMMIT() asm volatile("cp.async.commit_group;" ::: "memory")
#define CPA_WAIT0()  asm volatile("cp.async.wait_group 0;"  ::: "memory")
#define CPA_WAIT1()  asm volatile("cp.async.wait_group 1;"  ::: "memory")

__device__ __forceinline__ void ldsm4(uint32_t a, uint32_t* r) {
    asm volatile("ldmatrix.sync.aligned.m8n8.x4.shared.b16 {%0,%1,%2,%3}, [%4];"
        : "=r"(r[0]), "=r"(r[1]), "=r"(r[2]), "=r"(r[3]) : "r"(a));
}
__device__ __forceinline__ void mma16816(float* d, const uint32_t* a, const uint32_t* b) {
    asm volatile("mma.sync.aligned.m16n8k16.row.col.f32.bf16.bf16.f32 "
        "{%0,%1,%2,%3}, {%4,%5,%6,%7}, {%8,%9}, {%0,%1,%2,%3};"
        : "+f"(d[0]), "+f"(d[1]), "+f"(d[2]), "+f"(d[3])
        : "r"(a[0]), "r"(a[1]), "r"(a[2]), "r"(a[3]), "r"(b[0]), "r"(b[1]));
}

// ======== epilogue chunk maps ========
__constant__ int c_kind[31] = {0,0,0,0,0,0,0,0,0,0,0,0,1,1,1,1,0,0,0,1,0,0,0,0,0,1,1,1,1,1,1};
__constant__ int c_A[31]    = {320,152,304,304,304,304,304,152,152,152,152,152,
                               40,41,42,43, 152,208,416, 39, 208,152,416,360,152,
                               44,45,46,47,48,49};
__constant__ int c_B[31]    = {18,20,22,23,24,25,26,27,28,29,30,31,
                               0,2,3,5, 35,36,37, 1, 32,33,34,19,38,
                               4,4,4,4,4,4};
// blob: suit@0(40) rank@40(112) pos@152(56) action@208(96) active@304(16)
//       street@320(40) numpl@360(56) blind@416(16)

// ======== shared layout (bytes) ========
// fp32: blob 432f @0, sW 48f @432, sB 48f @480, bias 704f @528 -> 1232f = 4928B
#define B_P0H   4928
#define PLANEB  11776              /* 32 rows * 368B */
#define B_P0L   (B_P0H + PLANEB)
#define B_P1H   (B_P0L + PLANEB)
#define B_P1L   (B_P1H + PLANEB)
#define B_W     (B_P1L + PLANEB)   /* 52032 */
#define SLOTB   28160              /* max buffer: 80*88*2B*2 planes */
#define SMEM_BYTES (B_W + 2 * SLOTB)  /* 108352 -> 2 CTAs/SM */
#define PSTR    184                /* activation plane row stride in bf16 (368B, odd*16B) */

// split fp32 -> (hi, lo) bf16 pair-stores into both planes
__device__ __forceinline__ void split_store(bf16* H, bf16* Lp, int row, int k,
                                            float v0, float v1)
{
    bf16 h0 = __float2bfloat16_rn(v0), h1 = __float2bfloat16_rn(v1);
    bf16 l0 = __float2bfloat16_rn(v0 - __bfloat162float(h0));
    bf16 l1 = __float2bfloat16_rn(v1 - __bfloat162float(h1));
    uint32_t ph = (uint32_t)__bfloat16_as_ushort(h0) | ((uint32_t)__bfloat16_as_ushort(h1) << 16);
    uint32_t pl = (uint32_t)__bfloat16_as_ushort(l0) | ((uint32_t)__bfloat16_as_ushort(l1) << 16);
    *reinterpret_cast<uint32_t*>(H  + row * PSTR + k) = ph;
    *reinterpret_cast<uint32_t*>(Lp + row * PSTR + k) = pl;
}

// stage one weight buffer (hi+lo planes) into a slot; commits one cp.async group
__device__ __forceinline__ void stage_buf(char* smem, int slot,
                                          const bf16* gh, const bf16* gl,
                                          int nout, int nin, int kc, int kcur, int wstr)
{
    bf16* sh = reinterpret_cast<bf16*>(smem + B_W + slot * SLOTB);
    bf16* sl = sh + nout * wstr;
    int per = kcur >> 3;
    int tot = nout * per;
    for (int i = threadIdx.x; i < tot; i += NTHREADS) {
        int n = i / per, q = (i - n * per) << 3;
        cpa16(sh + n * wstr + q, gh + n * nin + kc + q);
        cpa16(sl + n * wstr + q, gl + n * nin + kc + q);
    }
    CPA_COMMIT();
}

// ======== one dense layer on tensor cores (3-pass bf16 split, paired-nb ldsm4 B) ========
// PRECONDITION: this layer's first chunk is staged in slot `slot` (in flight or done).
// Stages its own later chunks, then the next layer's first buffer, one unit ahead.
template<int NIN, int NOUT, int WSTR_, bool ACT, bool FINAL>
__device__ __forceinline__ void layer_mma(
    const bf16* __restrict__ srcH, const bf16* __restrict__ srcL,
    bf16* __restrict__ dstH, bf16* __restrict__ dstL,
    const bf16* __restrict__ gwh, const bf16* __restrict__ gwl,
    const float* __restrict__ bsm, char* smem, int& slot,
    const bf16* ngh, const bf16* ngl, int n_nout, int n_nin, int n_k0, int n_wstr,
    float* __restrict__ out, size_t g0)
{
    const int t = threadIdx.x, L = t & 31, wid = t >> 5;
    const int mb = wid & 1, pg = wid >> 1;          // 2 m-blocks x 4 pair-groups
    constexpr int CK    = (NIN <= 80) ? NIN : 32;
    constexpr int NCH   = (NIN + CK - 1) / CK;
    constexpr int NPAIR = NOUT / 16;
    constexpr int MAXP  = (NPAIR + 3) / 4;
    constexpr int PLANE = NOUT * WSTR_;             // elements per staged plane

    float acc[MAXP][2][4];
    #pragma unroll
    for (int i = 0; i < MAXP; i++)
        #pragma unroll
        for (int h = 0; h < 2; h++)
            #pragma unroll
            for (int q = 0; q < 4; q++) acc[i][h][q] = 0.0f;

    // A lane addressing (PTX x4 A-frag): row = mb*16 + L%16, col8 = (L/16)*8
    const int arow = mb * 16 + (L & 15);
    const uint32_t uAH = s2u(srcH + arow * PSTR + ((L >> 4) << 3));
    const uint32_t uAL = s2u(srcL + arow * PSTR + ((L >> 4) << 3));
    // B lane addressing for paired-nb x4: rows (L%8) + (L>=16)*8, col8 = ((L/8)&1)*8
    const int brow = (L & 7) + ((L >> 4) & 1) * 8;
    const int bcol = ((L >> 3) & 1) << 3;

    int kc = 0;
    #pragma unroll
    for (int c = 0; c < NCH; c++, kc += CK) {
        const int kcur = (c == NCH - 1) ? (NIN - CK * (NCH - 1)) : CK;
        __syncthreads();                 // all threads done with the other slot's old data
        bool staged;
        if (c + 1 < NCH) {
            int nk = NIN - kc - CK; if (nk > CK) nk = CK;
            stage_buf(smem, slot ^ 1, gwh, gwl, NOUT, NIN, kc + CK, nk, WSTR_);
            staged = true;
        } else if (ngh != nullptr) {
            stage_buf(smem, slot ^ 1, ngh, ngl, n_nout, n_nin, 0, n_k0, n_wstr);
            staged = true;
        } else staged = false;
        if (staged) { CPA_WAIT1(); } else { CPA_WAIT0(); }
        __syncthreads();                 // this chunk's weights visible to all

        const bf16* sbase = reinterpret_cast<const bf16*>(smem + B_W + slot * SLOTB);
        const uint32_t uBH = s2u(sbase + brow * WSTR_ + bcol);
        const uint32_t uBL = uBH + PLANE * 2;

        #pragma unroll
        for (int kb = 0; kb < kcur; kb += 16) {
            uint32_t ah[4], al[4];
            ldsm4(uAH + (kc + kb) * 2, ah);
            ldsm4(uAL + (kc + kb) * 2, al);
            #pragma unroll
            for (int i = 0; i < MAXP; i++) {
                int p = pg + 4 * i;
                if (p < NPAIR) {
                    uint32_t off = (uint32_t)(p * 16 * WSTR_ + kb) * 2;
                    uint32_t bh[4], bl[4];
                    ldsm4(uBH + off, bh);
                    ldsm4(uBL + off, bl);
                    mma16816(acc[i][0], ah, bh);
                    mma16816(acc[i][1], ah, bh + 2);
                    mma16816(acc[i][0], ah, bl);
                    mma16816(acc[i][1], ah, bl + 2);
                    mma16816(acc[i][0], al, bh);
                    mma16816(acc[i][1], al, bh + 2);
                }
            }
        }
        slot ^= 1;
    }

    // epilogue: D frag (r0 = L/4, c0 = 2(L%4); rows r0, r0+8)
    const int r0 = L >> 2, c0 = (L & 3) * 2;
    const int gr0 = mb * 16 + r0, gr1 = gr0 + 8;
    #pragma unroll
    for (int i = 0; i < MAXP; i++) {
        int p = pg + 4 * i;
        if (p < NPAIR) {
            #pragma unroll
            for (int h = 0; h < 2; h++) {
                int n0 = p * 16 + h * 8 + c0;
                float b0 = bsm[n0], b1 = bsm[n0 + 1];
                float v00 = acc[i][h][0] + b0, v01 = acc[i][h][1] + b1;
                float v10 = acc[i][h][2] + b0, v11 = acc[i][h][3] + b1;
                if (ACT) { v00 = lrelu(v00); v01 = lrelu(v01); v10 = lrelu(v10); v11 = lrelu(v11); }
                if (FINAL) {
                    *reinterpret_cast<float2*>(out + (g0 + gr0) * 312 + n0) = make_float2(v00, v01);
                    *reinterpret_cast<float2*>(out + (g0 + gr1) * 312 + n0) = make_float2(v10, v11);
                } else {
                    split_store(dstH, dstL, gr0, n0, v00, v01);
                    split_store(dstH, dstL, gr1, n0, v10, v11);
                }
            }
        }
    }
}

__global__ void __launch_bounds__(NTHREADS, 2)
preproc_kernel(const float* __restrict__ state,
               const float* __restrict__ suit_emb, const float* __restrict__ rank_emb,
               const float* __restrict__ hb1, const float* __restrict__ hb2,
               const float* __restrict__ hb3, const float* __restrict__ bb1,
               const float* __restrict__ bb2, const float* __restrict__ bb3,
               const float* __restrict__ cb1, const float* __restrict__ cb2,
               const float* __restrict__ cb3,
               const float* __restrict__ pos_emb, const float* __restrict__ action_emb,
               const float* __restrict__ active_emb, const float* __restrict__ street_emb,
               const float* __restrict__ numpl_emb, const float* __restrict__ blind_emb,
               const float* __restrict__ scalar_W, const float* __restrict__ scalar_b,
               float* __restrict__ out)
{
    extern __shared__ __align__(16) char smem[];
    float* fp   = reinterpret_cast<float*>(smem);
    float* blob = fp;
    float* sW   = fp + 432;
    float* sB   = fp + 480;
    float* bias = fp + 528;
    bf16* P0H = reinterpret_cast<bf16*>(smem + B_P0H);
    bf16* P0L = reinterpret_cast<bf16*>(smem + B_P0L);
    bf16* P1H = reinterpret_cast<bf16*>(smem + B_P1H);
    bf16* P1L = reinterpret_cast<bf16*>(smem + B_P1L);

    const int t = threadIdx.x;
    const size_t g0 = (size_t)blockIdx.x * TROWS;
    const float* st = state + g0 * 50;

    int slot = 0;
    // kick off h1 weight staging immediately (overlaps whole prologue)
    stage_buf(smem, 0, g_wh, g_wl, 64, 64, 0, 64, 72);

    // ---- stage tables + biases ----
    for (int i = t; i < 40;  i += NTHREADS) blob[0   + i] = suit_emb[i];
    for (int i = t; i < 112; i += NTHREADS) blob[40  + i] = rank_emb[i];
    for (int i = t; i < 56;  i += NTHREADS) blob[152 + i] = pos_emb[i];
    for (int i = t; i < 96;  i += NTHREADS) blob[208 + i] = action_emb[i];
    for (int i = t; i < 16;  i += NTHREADS) blob[304 + i] = active_emb[i];
    for (int i = t; i < 40;  i += NTHREADS) blob[320 + i] = street_emb[i];
    for (int i = t; i < 56;  i += NTHREADS) blob[360 + i] = numpl_emb[i];
    for (int i = t; i < 16;  i += NTHREADS) blob[416 + i] = blind_emb[i];
    for (int i = t; i < 48;  i += NTHREADS) { sW[i] = scalar_W[i]; sB[i] = scalar_b[i]; }
    for (int i = t; i < 64;  i += NTHREADS) bias[0   + i] = hb1[i];
    for (int i = t; i < 64;  i += NTHREADS) bias[64  + i] = hb2[i];
    for (int i = t; i < 64;  i += NTHREADS) bias[128 + i] = hb3[i];
    for (int i = t; i < 80;  i += NTHREADS) bias[192 + i] = bb1[i];
    for (int i = t; i < 80;  i += NTHREADS) bias[272 + i] = bb2[i];
    for (int i = t; i < 80;  i += NTHREADS) bias[352 + i] = bb3[i];
    for (int i = t; i < 144; i += NTHREADS) bias[432 + i] = cb1[i];
    for (int i = t; i < 64;  i += NTHREADS) bias[576 + i] = cb2[i];
    for (int i = t; i < 64;  i += NTHREADS) bias[640 + i] = cb3[i];
    __syncthreads();

    const float4* blob4 = reinterpret_cast<const float4*>(blob);

    // ---- cheap output columns 64..311: coalesced float4 stores ----
    for (int i = t; i < TROWS * 62; i += NTHREADS) {
        int r = i / 62, q = i - r * 62;
        int ch = q >> 1, half = q & 1;
        int kind = c_kind[ch], Ai = c_A[ch], Bc = c_B[ch];
        float4 v;
        if (kind == 0) {
            int xi = (int)__ldg(st + r * 50 + Bc);
            v = blob4[(Ai >> 2) + xi * 2 + half];
        } else {
            float s = __ldg(st + r * 50 + Ai);
            float4 w = *reinterpret_cast<const float4*>(sW + Bc * 8 + half * 4);
            float4 p = *reinterpret_cast<const float4*>(sB + Bc * 8 + half * 4);
            v = make_float4(s * w.x + p.x, s * w.y + p.y, s * w.z + p.z, s * w.w + p.w);
        }
        *reinterpret_cast<float4*>(out + (g0 + r) * 312 + 64 + q * 4) = v;
    }

    // ---- gather hand input (32 rows x 4 cards x 16 feats) -> P0 planes ----
    if (t < TROWS * 4) {
        int r = t >> 2, c = t & 3;
        int s  = (int)__ldg(st + r * 50 + 2 * c + 1);
        int rk = (int)__ldg(st + r * 50 + 2 * c);
        float v[16];
        *reinterpret_cast<float4*>(v)      = blob4[s * 2];
        *reinterpret_cast<float4*>(v + 4)  = blob4[s * 2 + 1];
        *reinterpret_cast<float4*>(v + 8)  = blob4[10 + rk * 2];
        *reinterpret_cast<float4*>(v + 12) = blob4[10 + rk * 2 + 1];
        #pragma unroll
        for (int p = 0; p < 8; p++)
            split_store(P0H, P0L, r, c * 16 + 2 * p, v[2 * p], v[2 * p + 1]);
    }
    // (visibility via h1 unit-0 barriers inside layer_mma)

    layer_mma<64, 64, 72, true,  false>(P0H, P0L, P1H, P1L, g_wh + 0,    g_wl + 0,    bias + 0,   smem, slot,
                                        g_wh + 4096,  g_wl + 4096,  64, 64, 64, 72, out, g0);
    layer_mma<64, 64, 72, true,  false>(P1H, P1L, P0H, P0L, g_wh + 4096, g_wl + 4096, bias + 64,  smem, slot,
                                        g_wh + 8192,  g_wl + 8192,  64, 64, 64, 72, out, g0);
    layer_mma<64, 64, 72, false, false>(P0H, P0L, P1H, P1L, g_wh + 8192, g_wl + 8192, bias + 128, smem, slot,
                                        g_wh + 12288, g_wl + 12288, 80, 80, 80, 88, out, g0);
    // hand output in P1[0:64)

    __syncthreads();  // all threads done reading P0 (h3 inputs) before board gather
    if (t < TROWS * 5) {
        int r = t / 5, c = t - r * 5;
        int s  = (int)__ldg(st + r * 50 + 9 + 2 * c);
        int rk = (int)__ldg(st + r * 50 + 8 + 2 * c);
        float v[16];
        *reinterpret_cast<float4*>(v)      = blob4[s * 2];
        *reinterpret_cast<float4*>(v + 4)  = blob4[s * 2 + 1];
        *reinterpret_cast<float4*>(v + 8)  = blob4[10 + rk * 2];
        *reinterpret_cast<float4*>(v + 12) = blob4[10 + rk * 2 + 1];
        #pragma unroll
        for (int p = 0; p < 8; p++)
            split_store(P0H, P0L, r, c * 16 + 2 * p, v[2 * p], v[2 * p + 1]);
    }

    layer_mma<80, 80, 88, true,  false>(P0H, P0L, P1H + 64, P1L + 64, g_wh + 12288, g_wl + 12288, bias + 192, smem, slot,
                                        g_wh + 18688, g_wl + 18688, 80, 80, 80, 88, out, g0);
    layer_mma<80, 80, 88, true,  false>(P1H + 64, P1L + 64, P0H, P0L, g_wh + 18688, g_wl + 18688, bias + 272, smem, slot,
                                        g_wh + 25088, g_wl + 25088, 80, 80, 80, 88, out, g0);
    layer_mma<80, 80, 88, false, false>(P0H, P0L, P1H + 64, P1L + 64, g_wh + 25088, g_wl + 25088, bias + 352, smem, slot,
                                        g_wh + 31488, g_wl + 31488, 144, 144, 32, 40, out, g0);
    // P1 holds concat[hand(0:64), board(64:144)]

    layer_mma<144, 144, 40, true, false>(P1H, P1L, P0H, P0L, g_wh + 31488, g_wl + 31488, bias + 432, smem, slot,
                                         g_wh + 52224, g_wl + 52224, 64, 144, 32, 40, out, g0);
    layer_mma<144, 64,  40, true, false>(P0H, P0L, P1H, P1L, g_wh + 52224, g_wl + 52224, bias + 576, smem, slot,
                                         g_wh + 61440, g_wl + 61440, 64, 64, 64, 72, out, g0);
    layer_mma<64,  64,  72, false, true>(P1H, P1L, P0H, P0L, g_wh + 61440, g_wl + 61440, bias + 640, smem, slot,
                                         nullptr, nullptr, 0, 0, 0, 0, out, g0);
}

extern "C" void kernel_launch(void* const* d_in, const int* in_sizes, int n_in,
                              void* d_out, int out_size)
{
    (void)n_in; (void)out_size;
    cudaFuncSetAttribute(preproc_kernel, cudaFuncAttributeMaxDynamicSharedMemorySize, SMEM_BYTES);

    // one-time-per-graph weight transpose + bf16 hi/lo split
    prep_kernel<<<256, 256>>>(
        (const float*)d_in[3],  (const float*)d_in[5],  (const float*)d_in[7],
        (const float*)d_in[9],  (const float*)d_in[11], (const float*)d_in[13],
        (const float*)d_in[15], (const float*)d_in[17], (const float*)d_in[19]);

    const int nrows = in_sizes[0] / 50;     // 262144
    const int grid  = nrows / TROWS;        // 8192

    preproc_kernel<<<grid, NTHREADS, SMEM_BYTES>>>(
        (const float*)d_in[0],
        (const float*)d_in[1],  (const float*)d_in[2],
        (const float*)d_in[4],  (const float*)d_in[6],  (const float*)d_in[8],
        (const float*)d_in[10], (const float*)d_in[12], (const float*)d_in[14],
        (const float*)d_in[16], (const float*)d_in[18], (const float*)d_in[20],
        (const float*)d_in[21], (const float*)d_in[22],
        (const float*)d_in[23], (const float*)d_in[24],
        (const float*)d_in[25], (const float*)d_in[26],
        (const float*)d_in[27], (const float*)d_in[28],
        (float*)d_out);
}

// round 14
// speedup vs baseline: 2.4032x; 1.6800x over previous
#include <cuda_runtime.h>
#include <cuda_bf16.h>
#include <cstddef>
#include <cstdint>

typedef __nv_bfloat16 bf16;

#define NTHREADS 256
#define TROWS 32

// ======== pre-packed B-fragment image ========
// For each (segment, kb, nb, lane): uint4 = {reg0_hi, reg1_hi, reg0_lo, reg1_lo}
// reg0 = (w[k0],w[k0+1]), reg1 = (w[k0+8],w[k0+9]); k0 = kb*16+2*(lane%4), n = nb*8+lane/4.
__device__ __align__(16) uint4 g_wf[16384];

__constant__ int f_pre[10]  = {0,1024,2048,3072,4672,6272,7872,13056,15360,16384};
__constant__ int f_nout[9]  = {64,64,64,80,80,80,144,64,64};

__device__ __forceinline__ uint32_t pack_bf2(bf16 a, bf16 b) {
    return (uint32_t)__bfloat16_as_ushort(a) | ((uint32_t)__bfloat16_as_ushort(b) << 16);
}

__global__ void prep_kernel(const float* w0,const float* w1,const float* w2,
                            const float* w3,const float* w4,const float* w5,
                            const float* w6,const float* w7,const float* w8)
{
    const float* W[9] = {w0,w1,w2,w3,w4,w5,w6,w7,w8};
    int i = blockIdx.x * blockDim.x + threadIdx.x;
    if (i >= 16384) return;
    int s = 0;
    while (i >= f_pre[s + 1]) s++;
    int f = i - f_pre[s];
    int nout = f_nout[s];
    int nbc = nout >> 3;
    int kb = f / (nbc * 32);
    int r  = f - kb * nbc * 32;
    int nb = r >> 5, lane = r & 31;
    int n  = nb * 8 + (lane >> 2);
    int k0 = kb * 16 + (lane & 3) * 2;
    const float* Ws = W[s];
    float w00 = Ws[(k0)     * nout + n];
    float w01 = Ws[(k0 + 1) * nout + n];
    float w10 = Ws[(k0 + 8) * nout + n];
    float w11 = Ws[(k0 + 9) * nout + n];
    bf16 h00 = __float2bfloat16_rn(w00), h01 = __float2bfloat16_rn(w01);
    bf16 h10 = __float2bfloat16_rn(w10), h11 = __float2bfloat16_rn(w11);
    bf16 l00 = __float2bfloat16_rn(w00 - __bfloat162float(h00));
    bf16 l01 = __float2bfloat16_rn(w01 - __bfloat162float(h01));
    bf16 l10 = __float2bfloat16_rn(w10 - __bfloat162float(h10));
    bf16 l11 = __float2bfloat16_rn(w11 - __bfloat162float(h11));
    uint4 v;
    v.x = pack_bf2(h00, h01);
    v.y = pack_bf2(h10, h11);
    v.z = pack_bf2(l00, l01);
    v.w = pack_bf2(l10, l11);
    g_wf[i] = v;
}

// ======== helpers ========
__device__ __forceinline__ float lrelu(float v) { return v > 0.0f ? v : 0.01f * v; }
__device__ __forceinline__ uint32_t s2u(const void* p) {
    return (uint32_t)__cvta_generic_to_shared(p);
}
__device__ __forceinline__ void ldsm4(uint32_t a, uint32_t* r) {
    asm volatile("ldmatrix.sync.aligned.m8n8.x4.shared.b16 {%0,%1,%2,%3}, [%4];"
        : "=r"(r[0]), "=r"(r[1]), "=r"(r[2]), "=r"(r[3]) : "r"(a));
}
__device__ __forceinline__ void mma16816(float* d, const uint32_t* a, uint32_t b0, uint32_t b1) {
    asm volatile("mma.sync.aligned.m16n8k16.row.col.f32.bf16.bf16.f32 "
        "{%0,%1,%2,%3}, {%4,%5,%6,%7}, {%8,%9}, {%0,%1,%2,%3};"
        : "+f"(d[0]), "+f"(d[1]), "+f"(d[2]), "+f"(d[3])
        : "r"(a[0]), "r"(a[1]), "r"(a[2]), "r"(a[3]), "r"(b0), "r"(b1));
}

// ======== epilogue chunk maps ========
__constant__ int c_kind[31] = {0,0,0,0,0,0,0,0,0,0,0,0,1,1,1,1,0,0,0,1,0,0,0,0,0,1,1,1,1,1,1};
__constant__ int c_A[31]    = {320,152,304,304,304,304,304,152,152,152,152,152,
                               40,41,42,43, 152,208,416, 39, 208,152,416,360,152,
                               44,45,46,47,48,49};
__constant__ int c_B[31]    = {18,20,22,23,24,25,26,27,28,29,30,31,
                               0,2,3,5, 35,36,37, 1, 32,33,34,19,38,
                               4,4,4,4,4,4};
// blob: suit@0(40) rank@40(112) pos@152(56) action@208(96) active@304(16)
//       street@320(40) numpl@360(56) blind@416(16)

// ======== shared layout (bytes) ========
// fp32: blob 432f @0, sW 48f @432, sB 48f @480, bias 704f @528 -> 1232f = 4928B
#define B_P0H   4928
#define PLANEB  11776              /* 32 rows * 368B */
#define B_P0L   (B_P0H + PLANEB)
#define B_P1H   (B_P0L + PLANEB)
#define B_P1L   (B_P1H + PLANEB)
#define SMEM_BYTES (B_P1L + PLANEB)   /* 52032 -> 3 CTAs/SM */
#define PSTR    184                /* activation plane row stride in bf16 (368B, odd*16B) */

// split fp32 -> (hi, lo) bf16 pair-stores into both planes
__device__ __forceinline__ void split_store(bf16* H, bf16* Lp, int row, int k,
                                            float v0, float v1)
{
    bf16 h0 = __float2bfloat16_rn(v0), h1 = __float2bfloat16_rn(v1);
    bf16 l0 = __float2bfloat16_rn(v0 - __bfloat162float(h0));
    bf16 l1 = __float2bfloat16_rn(v1 - __bfloat162float(h1));
    *reinterpret_cast<uint32_t*>(H  + row * PSTR + k) = pack_bf2(h0, h1);
    *reinterpret_cast<uint32_t*>(Lp + row * PSTR + k) = pack_bf2(l0, l1);
}

// ======== one dense layer: 3-pass bf16 split, B frags direct from global ========
template<int NIN, int NOUT, bool ACT, bool FINAL>
__device__ __forceinline__ void layer_mma(
    const bf16* __restrict__ srcH, const bf16* __restrict__ srcL,
    bf16* __restrict__ dstH, bf16* __restrict__ dstL,
    const uint4* __restrict__ wf,
    const float* __restrict__ bsm,
    float* __restrict__ out, size_t g0)
{
    const int t = threadIdx.x, L = t & 31, wid = t >> 5;
    const int mb = wid & 1, pg = wid >> 1;          // 2 m-blocks x 4 pair-groups
    constexpr int NKB   = NIN / 16;
    constexpr int NPAIR = NOUT / 16;
    constexpr int NBC   = NOUT / 8;
    constexpr int MAXP  = (NPAIR + 3) / 4;

    __syncthreads();   // previous layer's activations fully written

    float acc[MAXP][2][4];
    #pragma unroll
    for (int i = 0; i < MAXP; i++)
        #pragma unroll
        for (int h = 0; h < 2; h++)
            #pragma unroll
            for (int q = 0; q < 4; q++) acc[i][h][q] = 0.0f;

    // A lane addressing (PTX x4 A-frag): row = mb*16 + L%16, col8 = (L/16)*8
    const int arow = mb * 16 + (L & 15);
    const uint32_t uAH = s2u(srcH + arow * PSTR + ((L >> 4) << 3));
    const uint32_t uAL = s2u(srcL + arow * PSTR + ((L >> 4) << 3));
    const uint4* wlane = wf + L;

    #pragma unroll
    for (int kb = 0; kb < NKB; kb++) {
        uint32_t ah[4], al[4];
        ldsm4(uAH + kb * 32, ah);
        ldsm4(uAL + kb * 32, al);
        #pragma unroll
        for (int i = 0; i < MAXP; i++) {
            int p = pg + 4 * i;
            if (p < NPAIR) {
                const uint4* fp = wlane + (kb * NBC + 2 * p) * 32;
                uint4 f0 = __ldg(fp);
                uint4 f1 = __ldg(fp + 32);
                mma16816(acc[i][0], ah, f0.x, f0.y);   // xh * wh (nb0)
                mma16816(acc[i][1], ah, f1.x, f1.y);   // xh * wh (nb1)
                mma16816(acc[i][0], ah, f0.z, f0.w);   // xh * wl
                mma16816(acc[i][1], ah, f1.z, f1.w);
                mma16816(acc[i][0], al, f0.x, f0.y);   // xl * wh
                mma16816(acc[i][1], al, f1.x, f1.y);
            }
        }
    }

    // epilogue: D frag (r0 = L/4, c0 = 2(L%4); rows r0, r0+8)
    const int r0 = L >> 2, c0 = (L & 3) * 2;
    const int gr0 = mb * 16 + r0, gr1 = gr0 + 8;
    #pragma unroll
    for (int i = 0; i < MAXP; i++) {
        int p = pg + 4 * i;
        if (p < NPAIR) {
            #pragma unroll
            for (int h = 0; h < 2; h++) {
                int n0 = p * 16 + h * 8 + c0;
                float b0 = bsm[n0], b1 = bsm[n0 + 1];
                float v00 = acc[i][h][0] + b0, v01 = acc[i][h][1] + b1;
                float v10 = acc[i][h][2] + b0, v11 = acc[i][h][3] + b1;
                if (ACT) { v00 = lrelu(v00); v01 = lrelu(v01); v10 = lrelu(v10); v11 = lrelu(v11); }
                if (FINAL) {
                    *reinterpret_cast<float2*>(out + (g0 + gr0) * 312 + n0) = make_float2(v00, v01);
                    *reinterpret_cast<float2*>(out + (g0 + gr1) * 312 + n0) = make_float2(v10, v11);
                } else {
                    split_store(dstH, dstL, gr0, n0, v00, v01);
                    split_store(dstH, dstL, gr1, n0, v10, v11);
                }
            }
        }
    }
}

__global__ void __launch_bounds__(NTHREADS, 3)
preproc_kernel(const float* __restrict__ state,
               const float* __restrict__ suit_emb, const float* __restrict__ rank_emb,
               const float* __restrict__ hb1, const float* __restrict__ hb2,
               const float* __restrict__ hb3, const float* __restrict__ bb1,
               const float* __restrict__ bb2, const float* __restrict__ bb3,
               const float* __restrict__ cb1, const float* __restrict__ cb2,
               const float* __restrict__ cb3,
               const float* __restrict__ pos_emb, const float* __restrict__ action_emb,
               const float* __restrict__ active_emb, const float* __restrict__ street_emb,
               const float* __restrict__ numpl_emb, const float* __restrict__ blind_emb,
               const float* __restrict__ scalar_W, const float* __restrict__ scalar_b,
               float* __restrict__ out)
{
    extern __shared__ __align__(16) char smem[];
    float* fp   = reinterpret_cast<float*>(smem);
    float* blob = fp;
    float* sW   = fp + 432;
    float* sB   = fp + 480;
    float* bias = fp + 528;
    bf16* P0H = reinterpret_cast<bf16*>(smem + B_P0H);
    bf16* P0L = reinterpret_cast<bf16*>(smem + B_P0L);
    bf16* P1H = reinterpret_cast<bf16*>(smem + B_P1H);
    bf16* P1L = reinterpret_cast<bf16*>(smem + B_P1L);

    const int t = threadIdx.x;
    const size_t g0 = (size_t)blockIdx.x * TROWS;
    const float* st = state + g0 * 50;

    // ---- stage tables + biases ----
    for (int i = t; i < 40;  i += NTHREADS) blob[0   + i] = suit_emb[i];
    for (int i = t; i < 112; i += NTHREADS) blob[40  + i] = rank_emb[i];
    for (int i = t; i < 56;  i += NTHREADS) blob[152 + i] = pos_emb[i];
    for (int i = t; i < 96;  i += NTHREADS) blob[208 + i] = action_emb[i];
    for (int i = t; i < 16;  i += NTHREADS) blob[304 + i] = active_emb[i];
    for (int i = t; i < 40;  i += NTHREADS) blob[320 + i] = street_emb[i];
    for (int i = t; i < 56;  i += NTHREADS) blob[360 + i] = numpl_emb[i];
    for (int i = t; i < 16;  i += NTHREADS) blob[416 + i] = blind_emb[i];
    for (int i = t; i < 48;  i += NTHREADS) { sW[i] = scalar_W[i]; sB[i] = scalar_b[i]; }
    for (int i = t; i < 64;  i += NTHREADS) bias[0   + i] = hb1[i];
    for (int i = t; i < 64;  i += NTHREADS) bias[64  + i] = hb2[i];
    for (int i = t; i < 64;  i += NTHREADS) bias[128 + i] = hb3[i];
    for (int i = t; i < 80;  i += NTHREADS) bias[192 + i] = bb1[i];
    for (int i = t; i < 80;  i += NTHREADS) bias[272 + i] = bb2[i];
    for (int i = t; i < 80;  i += NTHREADS) bias[352 + i] = bb3[i];
    for (int i = t; i < 144; i += NTHREADS) bias[432 + i] = cb1[i];
    for (int i = t; i < 64;  i += NTHREADS) bias[576 + i] = cb2[i];
    for (int i = t; i < 64;  i += NTHREADS) bias[640 + i] = cb3[i];
    __syncthreads();

    const float4* blob4 = reinterpret_cast<const float4*>(blob);

    // ---- cheap output columns 64..311: coalesced float4 stores ----
    for (int i = t; i < TROWS * 62; i += NTHREADS) {
        int r = i / 62, q = i - r * 62;
        int ch = q >> 1, half = q & 1;
        int kind = c_kind[ch], Ai = c_A[ch], Bc = c_B[ch];
        float4 v;
        if (kind == 0) {
            int xi = (int)__ldg(st + r * 50 + Bc);
            v = blob4[(Ai >> 2) + xi * 2 + half];
        } else {
            float s = __ldg(st + r * 50 + Ai);
            float4 w = *reinterpret_cast<const float4*>(sW + Bc * 8 + half * 4);
            float4 p = *reinterpret_cast<const float4*>(sB + Bc * 8 + half * 4);
            v = make_float4(s * w.x + p.x, s * w.y + p.y, s * w.z + p.z, s * w.w + p.w);
        }
        *reinterpret_cast<float4*>(out + (g0 + r) * 312 + 64 + q * 4) = v;
    }

    // ---- gather hand input (32 rows x 4 cards x 16 feats) -> P0 planes ----
    if (t < TROWS * 4) {
        int r = t >> 2, c = t & 3;
        int s  = (int)__ldg(st + r * 50 + 2 * c + 1);
        int rk = (int)__ldg(st + r * 50 + 2 * c);
        float v[16];
        *reinterpret_cast<float4*>(v)      = blob4[s * 2];
        *reinterpret_cast<float4*>(v + 4)  = blob4[s * 2 + 1];
        *reinterpret_cast<float4*>(v + 8)  = blob4[10 + rk * 2];
        *reinterpret_cast<float4*>(v + 12) = blob4[10 + rk * 2 + 1];
        #pragma unroll
        for (int p = 0; p < 8; p++)
            split_store(P0H, P0L, r, c * 16 + 2 * p, v[2 * p], v[2 * p + 1]);
    }
    // (h1's entry barrier establishes visibility)

    layer_mma<64, 64, true,  false>(P0H, P0L, P1H, P1L, g_wf + 0,    bias + 0,   out, g0);
    layer_mma<64, 64, true,  false>(P1H, P1L, P0H, P0L, g_wf + 1024, bias + 64,  out, g0);
    layer_mma<64, 64, false, false>(P0H, P0L, P1H, P1L, g_wf + 2048, bias + 128, out, g0);
    // hand output in P1[0:64)

    __syncthreads();  // h3 warps done reading P0 before board gather overwrites
    if (t < TROWS * 5) {
        int r = t / 5, c = t - r * 5;
        int s  = (int)__ldg(st + r * 50 + 9 + 2 * c);
        int rk = (int)__ldg(st + r * 50 + 8 + 2 * c);
        float v[16];
        *reinterpret_cast<float4*>(v)      = blob4[s * 2];
        *reinterpret_cast<float4*>(v + 4)  = blob4[s * 2 + 1];
        *reinterpret_cast<float4*>(v + 8)  = blob4[10 + rk * 2];
        *reinterpret_cast<float4*>(v + 12) = blob4[10 + rk * 2 + 1];
        #pragma unroll
        for (int p = 0; p < 8; p++)
            split_store(P0H, P0L, r, c * 16 + 2 * p, v[2 * p], v[2 * p + 1]);
    }

    layer_mma<80, 80, true,  false>(P0H, P0L, P1H + 64, P1L + 64, g_wf + 3072, bias + 192, out, g0);
    layer_mma<80, 80, true,  false>(P1H + 64, P1L + 64, P0H, P0L, g_wf + 4672, bias + 272, out, g0);
    layer_mma<80, 80, false, false>(P0H, P0L, P1H + 64, P1L + 64, g_wf + 6272, bias + 352, out, g0);
    // P1 holds concat[hand(0:64), board(64:144)]

    layer_mma<144, 144, true, false>(P1H, P1L, P0H, P0L, g_wf + 7872,  bias + 432, out, g0);
    layer_mma<144, 64,  true, false>(P0H, P0L, P1H, P1L, g_wf + 13056, bias + 576, out, g0);
    layer_mma<64,  64, false, true >(P1H, P1L, P0H, P0L, g_wf + 15360, bias + 640, out, g0);
}

extern "C" void kernel_launch(void* const* d_in, const int* in_sizes, int n_in,
                              void* d_out, int out_size)
{
    (void)n_in; (void)out_size;
    cudaFuncSetAttribute(preproc_kernel, cudaFuncAttributeMaxDynamicSharedMemorySize, SMEM_BYTES);

    // one-time-per-graph fragment packing (bf16 hi/lo split, mma-lane layout)
    prep_kernel<<<64, 256>>>(
        (const float*)d_in[3],  (const float*)d_in[5],  (const float*)d_in[7],
        (const float*)d_in[9],  (const float*)d_in[11], (const float*)d_in[13],
        (const float*)d_in[15], (const float*)d_in[17], (const float*)d_in[19]);

    const int nrows = in_sizes[0] / 50;     // 262144
    const int grid  = nrows / TROWS;        // 8192

    preproc_kernel<<<grid, NTHREADS, SMEM_BYTES>>>(
        (const float*)d_in[0],
        (const float*)d_in[1],  (const float*)d_in[2],
        (const float*)d_in[4],  (const float*)d_in[6],  (const float*)d_in[8],
        (const float*)d_in[10], (const float*)d_in[12], (const float*)d_in[14],
        (const float*)d_in[16], (const float*)d_in[18], (const float*)d_in[20],
        (const float*)d_in[21], (const float*)d_in[22],
        (const float*)d_in[23], (const float*)d_in[24],
        (const float*)d_in[25], (const float*)d_in[26],
        (const float*)d_in[27], (const float*)d_in[28],
        (float*)d_out);
}

// round 15
// speedup vs baseline: 2.4064x; 1.0013x over previous
#include <cuda_runtime.h>
#include <cuda_bf16.h>
#include <cstddef>
#include <cstdint>

typedef __nv_bfloat16 bf16;

#define NTHREADS 256
#define TROWS 32

// ======== pre-packed B-fragment image ========
// For each (segment, kb, nb, lane): uint4 = {reg0_hi, reg1_hi, reg0_lo, reg1_lo}
// reg0 = (w[k0],w[k0+1]), reg1 = (w[k0+8],w[k0+9]); k0 = kb*16+2*(lane%4), n = nb*8+lane/4.
__device__ __align__(16) uint4 g_wf[16384];

__constant__ int f_pre[10]  = {0,1024,2048,3072,4672,6272,7872,13056,15360,16384};
__constant__ int f_nout[9]  = {64,64,64,80,80,80,144,64,64};

__device__ __forceinline__ uint32_t pack_bf2(bf16 a, bf16 b) {
    return (uint32_t)__bfloat16_as_ushort(a) | ((uint32_t)__bfloat16_as_ushort(b) << 16);
}

__global__ void prep_kernel(const float* w0,const float* w1,const float* w2,
                            const float* w3,const float* w4,const float* w5,
                            const float* w6,const float* w7,const float* w8)
{
    const float* W[9] = {w0,w1,w2,w3,w4,w5,w6,w7,w8};
    int i = blockIdx.x * blockDim.x + threadIdx.x;
    if (i >= 16384) return;
    int s = 0;
    while (i >= f_pre[s + 1]) s++;
    int f = i - f_pre[s];
    int nout = f_nout[s];
    int nbc = nout >> 3;
    int kb = f / (nbc * 32);
    int r  = f - kb * nbc * 32;
    int nb = r >> 5, lane = r & 31;
    int n  = nb * 8 + (lane >> 2);
    int k0 = kb * 16 + (lane & 3) * 2;
    const float* Ws = W[s];
    float w00 = Ws[(k0)     * nout + n];
    float w01 = Ws[(k0 + 1) * nout + n];
    float w10 = Ws[(k0 + 8) * nout + n];
    float w11 = Ws[(k0 + 9) * nout + n];
    bf16 h00 = __float2bfloat16_rn(w00), h01 = __float2bfloat16_rn(w01);
    bf16 h10 = __float2bfloat16_rn(w10), h11 = __float2bfloat16_rn(w11);
    bf16 l00 = __float2bfloat16_rn(w00 - __bfloat162float(h00));
    bf16 l01 = __float2bfloat16_rn(w01 - __bfloat162float(h01));
    bf16 l10 = __float2bfloat16_rn(w10 - __bfloat162float(h10));
    bf16 l11 = __float2bfloat16_rn(w11 - __bfloat162float(h11));
    uint4 v;
    v.x = pack_bf2(h00, h01);
    v.y = pack_bf2(h10, h11);
    v.z = pack_bf2(l00, l01);
    v.w = pack_bf2(l10, l11);
    g_wf[i] = v;
}

// ======== helpers ========
__device__ __forceinline__ float lrelu(float v) { return v > 0.0f ? v : 0.01f * v; }
__device__ __forceinline__ uint32_t s2u(const void* p) {
    return (uint32_t)__cvta_generic_to_shared(p);
}
__device__ __forceinline__ void ldsm4(uint32_t a, uint32_t* r) {
    asm volatile("ldmatrix.sync.aligned.m8n8.x4.shared.b16 {%0,%1,%2,%3}, [%4];"
        : "=r"(r[0]), "=r"(r[1]), "=r"(r[2]), "=r"(r[3]) : "r"(a));
}
__device__ __forceinline__ void mma16816(float* d, const uint32_t* a, uint32_t b0, uint32_t b1) {
    asm volatile("mma.sync.aligned.m16n8k16.row.col.f32.bf16.bf16.f32 "
        "{%0,%1,%2,%3}, {%4,%5,%6,%7}, {%8,%9}, {%0,%1,%2,%3};"
        : "+f"(d[0]), "+f"(d[1]), "+f"(d[2]), "+f"(d[3])
        : "r"(a[0]), "r"(a[1]), "r"(a[2]), "r"(a[3]), "r"(b0), "r"(b1));
}

// ======== epilogue chunk maps ========
__constant__ int c_kind[31] = {0,0,0,0,0,0,0,0,0,0,0,0,1,1,1,1,0,0,0,1,0,0,0,0,0,1,1,1,1,1,1};
__constant__ int c_A[31]    = {320,152,304,304,304,304,304,152,152,152,152,152,
                               40,41,42,43, 152,208,416, 39, 208,152,416,360,152,
                               44,45,46,47,48,49};
__constant__ int c_B[31]    = {18,20,22,23,24,25,26,27,28,29,30,31,
                               0,2,3,5, 35,36,37, 1, 32,33,34,19,38,
                               4,4,4,4,4,4};
// blob: suit@0(40) rank@40(112) pos@152(56) action@208(96) active@304(16)
//       street@320(40) numpl@360(56) blind@416(16)

// ======== shared layout (bytes) ========
// fp32: blob 432f @0, sW 48f @432, sB 48f @480, bias 704f @528 -> 1232f = 4928B
#define B_P0H   4928
#define PLANEB  11776              /* 32 rows * 368B */
#define B_P0L   (B_P0H + PLANEB)
#define B_P1H   (B_P0L + PLANEB)
#define B_P1L   (B_P1H + PLANEB)
#define SMEM_BYTES (B_P1L + PLANEB)   /* 52032 -> 4 CTAs/SM (smem) */
#define PSTR    184                /* activation plane row stride in bf16 (368B, odd*16B) */

// split fp32 -> (hi, lo) bf16 pair-stores into both planes
__device__ __forceinline__ void split_store(bf16* H, bf16* Lp, int row, int k,
                                            float v0, float v1)
{
    bf16 h0 = __float2bfloat16_rn(v0), h1 = __float2bfloat16_rn(v1);
    bf16 l0 = __float2bfloat16_rn(v0 - __bfloat162float(h0));
    bf16 l1 = __float2bfloat16_rn(v1 - __bfloat162float(h1));
    *reinterpret_cast<uint32_t*>(H  + row * PSTR + k) = pack_bf2(h0, h1);
    *reinterpret_cast<uint32_t*>(Lp + row * PSTR + k) = pack_bf2(l0, l1);
}

// ======== one dense (sub-)layer: 3-pass bf16 split, B frags direct from global ========
// Computes n-pairs [PAIR0, PAIR0+NPS) of a segment whose full width is NOUTG.
template<int NIN, int NOUTG, int PAIR0, int NPS, bool ACT, bool FINAL>
__device__ __forceinline__ void layer_mma(
    const bf16* __restrict__ srcH, const bf16* __restrict__ srcL,
    bf16* __restrict__ dstH, bf16* __restrict__ dstL,
    const uint4* __restrict__ wf,
    const float* __restrict__ bsm,
    float* __restrict__ out, size_t g0)
{
    const int t = threadIdx.x, L = t & 31, wid = t >> 5;
    const int mb = wid & 1, pg = wid >> 1;          // 2 m-blocks x 4 pair-groups
    constexpr int NKB  = NIN / 16;
    constexpr int NBC  = NOUTG / 8;
    constexpr int MAXP = (NPS + 3) / 4;

    __syncthreads();   // previous layer's activations fully written

    float acc[MAXP][2][4];
    #pragma unroll
    for (int i = 0; i < MAXP; i++)
        #pragma unroll
        for (int h = 0; h < 2; h++)
            #pragma unroll
            for (int q = 0; q < 4; q++) acc[i][h][q] = 0.0f;

    // A lane addressing (PTX x4 A-frag): row = mb*16 + L%16, col8 = (L/16)*8
    const int arow = mb * 16 + (L & 15);
    const uint32_t uAH = s2u(srcH + arow * PSTR + ((L >> 4) << 3));
    const uint32_t uAL = s2u(srcL + arow * PSTR + ((L >> 4) << 3));
    const uint4* wlane = wf + L;

    #pragma unroll
    for (int kb = 0; kb < NKB; kb++) {
        uint32_t ah[4], al[4];
        ldsm4(uAH + kb * 32, ah);
        ldsm4(uAL + kb * 32, al);
        #pragma unroll
        for (int i = 0; i < MAXP; i++) {
            int p = pg + 4 * i;
            if (p < NPS) {
                const uint4* fp = wlane + (kb * NBC + 2 * (PAIR0 + p)) * 32;
                uint4 f0 = __ldg(fp);
                uint4 f1 = __ldg(fp + 32);
                mma16816(acc[i][0], ah, f0.x, f0.y);   // xh * wh (nb0)
                mma16816(acc[i][1], ah, f1.x, f1.y);   // xh * wh (nb1)
                mma16816(acc[i][0], ah, f0.z, f0.w);   // xh * wl
                mma16816(acc[i][1], ah, f1.z, f1.w);
                mma16816(acc[i][0], al, f0.x, f0.y);   // xl * wh
                mma16816(acc[i][1], al, f1.x, f1.y);
            }
        }
    }

    // epilogue: D frag (r0 = L/4, c0 = 2(L%4); rows r0, r0+8)
    const int r0 = L >> 2, c0 = (L & 3) * 2;
    const int gr0 = mb * 16 + r0, gr1 = gr0 + 8;
    #pragma unroll
    for (int i = 0; i < MAXP; i++) {
        int p = pg + 4 * i;
        if (p < NPS) {
            #pragma unroll
            for (int h = 0; h < 2; h++) {
                int n0 = (PAIR0 + p) * 16 + h * 8 + c0;
                float b0 = bsm[n0], b1 = bsm[n0 + 1];
                float v00 = acc[i][h][0] + b0, v01 = acc[i][h][1] + b1;
                float v10 = acc[i][h][2] + b0, v11 = acc[i][h][3] + b1;
                if (ACT) { v00 = lrelu(v00); v01 = lrelu(v01); v10 = lrelu(v10); v11 = lrelu(v11); }
                if (FINAL) {
                    *reinterpret_cast<float2*>(out + (g0 + gr0) * 312 + n0) = make_float2(v00, v01);
                    *reinterpret_cast<float2*>(out + (g0 + gr1) * 312 + n0) = make_float2(v10, v11);
                } else {
                    split_store(dstH, dstL, gr0, n0, v00, v01);
                    split_store(dstH, dstL, gr1, n0, v10, v11);
                }
            }
        }
    }
}

__global__ void __launch_bounds__(NTHREADS, 4)
preproc_kernel(const float* __restrict__ state,
               const float* __restrict__ suit_emb, const float* __restrict__ rank_emb,
               const float* __restrict__ hb1, const float* __restrict__ hb2,
               const float* __restrict__ hb3, const float* __restrict__ bb1,
               const float* __restrict__ bb2, const float* __restrict__ bb3,
               const float* __restrict__ cb1, const float* __restrict__ cb2,
               const float* __restrict__ cb3,
               const float* __restrict__ pos_emb, const float* __restrict__ action_emb,
               const float* __restrict__ active_emb, const float* __restrict__ street_emb,
               const float* __restrict__ numpl_emb, const float* __restrict__ blind_emb,
               const float* __restrict__ scalar_W, const float* __restrict__ scalar_b,
               float* __restrict__ out)
{
    extern __shared__ __align__(16) char smem[];
    float* fp   = reinterpret_cast<float*>(smem);
    float* blob = fp;
    float* sW   = fp + 432;
    float* sB   = fp + 480;
    float* bias = fp + 528;
    bf16* P0H = reinterpret_cast<bf16*>(smem + B_P0H);
    bf16* P0L = reinterpret_cast<bf16*>(smem + B_P0L);
    bf16* P1H = reinterpret_cast<bf16*>(smem + B_P1H);
    bf16* P1L = reinterpret_cast<bf16*>(smem + B_P1L);

    const int t = threadIdx.x;
    const size_t g0 = (size_t)blockIdx.x * TROWS;
    const float* st = state + g0 * 50;

    // ---- stage tables + biases ----
    for (int i = t; i < 40;  i += NTHREADS) blob[0   + i] = suit_emb[i];
    for (int i = t; i < 112; i += NTHREADS) blob[40  + i] = rank_emb[i];
    for (int i = t; i < 56;  i += NTHREADS) blob[152 + i] = pos_emb[i];
    for (int i = t; i < 96;  i += NTHREADS) blob[208 + i] = action_emb[i];
    for (int i = t; i < 16;  i += NTHREADS) blob[304 + i] = active_emb[i];
    for (int i = t; i < 40;  i += NTHREADS) blob[320 + i] = street_emb[i];
    for (int i = t; i < 56;  i += NTHREADS) blob[360 + i] = numpl_emb[i];
    for (int i = t; i < 16;  i += NTHREADS) blob[416 + i] = blind_emb[i];
    for (int i = t; i < 48;  i += NTHREADS) { sW[i] = scalar_W[i]; sB[i] = scalar_b[i]; }
    for (int i = t; i < 64;  i += NTHREADS) bias[0   + i] = hb1[i];
    for (int i = t; i < 64;  i += NTHREADS) bias[64  + i] = hb2[i];
    for (int i = t; i < 64;  i += NTHREADS) bias[128 + i] = hb3[i];
    for (int i = t; i < 80;  i += NTHREADS) bias[192 + i] = bb1[i];
    for (int i = t; i < 80;  i += NTHREADS) bias[272 + i] = bb2[i];
    for (int i = t; i < 80;  i += NTHREADS) bias[352 + i] = bb3[i];
    for (int i = t; i < 144; i += NTHREADS) bias[432 + i] = cb1[i];
    for (int i = t; i < 64;  i += NTHREADS) bias[576 + i] = cb2[i];
    for (int i = t; i < 64;  i += NTHREADS) bias[640 + i] = cb3[i];
    __syncthreads();

    const float4* blob4 = reinterpret_cast<const float4*>(blob);

    // ---- cheap output columns 64..311: coalesced float4 stores ----
    for (int i = t; i < TROWS * 62; i += NTHREADS) {
        int r = i / 62, q = i - r * 62;
        int ch = q >> 1, half = q & 1;
        int kind = c_kind[ch], Ai = c_A[ch], Bc = c_B[ch];
        float4 v;
        if (kind == 0) {
            int xi = (int)__ldg(st + r * 50 + Bc);
            v = blob4[(Ai >> 2) + xi * 2 + half];
        } else {
            float s = __ldg(st + r * 50 + Ai);
            float4 w = *reinterpret_cast<const float4*>(sW + Bc * 8 + half * 4);
            float4 p = *reinterpret_cast<const float4*>(sB + Bc * 8 + half * 4);
            v = make_float4(s * w.x + p.x, s * w.y + p.y, s * w.z + p.z, s * w.w + p.w);
        }
        *reinterpret_cast<float4*>(out + (g0 + r) * 312 + 64 + q * 4) = v;
    }

    // ---- gather hand input (32 rows x 4 cards x 16 feats) -> P0 planes ----
    if (t < TROWS * 4) {
        int r = t >> 2, c = t & 3;
        int s  = (int)__ldg(st + r * 50 + 2 * c + 1);
        int rk = (int)__ldg(st + r * 50 + 2 * c);
        float v[16];
        *reinterpret_cast<float4*>(v)      = blob4[s * 2];
        *reinterpret_cast<float4*>(v + 4)  = blob4[s * 2 + 1];
        *reinterpret_cast<float4*>(v + 8)  = blob4[10 + rk * 2];
        *reinterpret_cast<float4*>(v + 12) = blob4[10 + rk * 2 + 1];
        #pragma unroll
        for (int p = 0; p < 8; p++)
            split_store(P0H, P0L, r, c * 16 + 2 * p, v[2 * p], v[2 * p + 1]);
    }
    // (h1's entry barrier establishes visibility)

    layer_mma<64, 64, 0, 4, true,  false>(P0H, P0L, P1H, P1L, g_wf + 0,    bias + 0,   out, g0);
    layer_mma<64, 64, 0, 4, true,  false>(P1H, P1L, P0H, P0L, g_wf + 1024, bias + 64,  out, g0);
    layer_mma<64, 64, 0, 4, false, false>(P0H, P0L, P1H, P1L, g_wf + 2048, bias + 128, out, g0);
    // hand output in P1[0:64)

    __syncthreads();  // h3 warps done reading P0 before board gather overwrites
    if (t < TROWS * 5) {
        int r = t / 5, c = t - r * 5;
        int s  = (int)__ldg(st + r * 50 + 9 + 2 * c);
        int rk = (int)__ldg(st + r * 50 + 8 + 2 * c);
        float v[16];
        *reinterpret_cast<float4*>(v)      = blob4[s * 2];
        *reinterpret_cast<float4*>(v + 4)  = blob4[s * 2 + 1];
        *reinterpret_cast<float4*>(v + 8)  = blob4[10 + rk * 2];
        *reinterpret_cast<float4*>(v + 12) = blob4[10 + rk * 2 + 1];
        #pragma unroll
        for (int p = 0; p < 8; p++)
            split_store(P0H, P0L, r, c * 16 + 2 * p, v[2 * p], v[2 * p + 1]);
    }

    layer_mma<80, 80, 0, 5, true,  false>(P0H, P0L, P1H + 64, P1L + 64, g_wf + 3072, bias + 192, out, g0);
    layer_mma<80, 80, 0, 5, true,  false>(P1H + 64, P1L + 64, P0H, P0L, g_wf + 4672, bias + 272, out, g0);
    layer_mma<80, 80, 0, 5, false, false>(P0H, P0L, P1H + 64, P1L + 64, g_wf + 6272, bias + 352, out, g0);
    // P1 holds concat[hand(0:64), board(64:144)]

    // c1 split into two n-slices (pairs 0..4, then 5..8) to keep MAXP<=2 (reg diet)
    layer_mma<144, 144, 0, 5, true, false>(P1H, P1L, P0H, P0L, g_wf + 7872, bias + 432, out, g0);
    layer_mma<144, 144, 5, 4, true, false>(P1H, P1L, P0H, P0L, g_wf + 7872, bias + 432, out, g0);
    layer_mma<144, 64,  0, 4, true, false>(P0H, P0L, P1H, P1L, g_wf + 13056, bias + 576, out, g0);
    layer_mma<64,  64,  0, 4, false, true>(P1H, P1L, P0H, P0L, g_wf + 15360, bias + 640, out, g0);
}

extern "C" void kernel_launch(void* const* d_in, const int* in_sizes, int n_in,
                              void* d_out, int out_size)
{
    (void)n_in; (void)out_size;
    cudaFuncSetAttribute(preproc_kernel, cudaFuncAttributeMaxDynamicSharedMemorySize, SMEM_BYTES);

    // one-time-per-graph fragment packing (bf16 hi/lo split, mma-lane layout)
    prep_kernel<<<64, 256>>>(
        (const float*)d_in[3],  (const float*)d_in[5],  (const float*)d_in[7],
        (const float*)d_in[9],  (const float*)d_in[11], (const float*)d_in[13],
        (const float*)d_in[15], (const float*)d_in[17], (const float*)d_in[19]);

    const int nrows = in_sizes[0] / 50;     // 262144
    const int grid  = nrows / TROWS;        // 8192

    preproc_kernel<<<grid, NTHREADS, SMEM_BYTES>>>(
        (const float*)d_in[0],
        (const float*)d_in[1],  (const float*)d_in[2],
        (const float*)d_in[4],  (const float*)d_in[6],  (const float*)d_in[8],
        (const float*)d_in[10], (const float*)d_in[12], (const float*)d_in[14],
        (const float*)d_in[16], (const float*)d_in[18], (const float*)d_in[20],
        (const float*)d_in[21], (const float*)d_in[22],
        (const float*)d_in[23], (const float*)d_in[24],
        (const float*)d_in[25], (const float*)d_in[26],
        (const float*)d_in[27], (const float*)d_in[28],
        (float*)d_out);
}